// round 10
// baseline (speedup 1.0000x reference)
#include <cuda_runtime.h>
#include <cuda_bf16.h>
#include <cstdint>

// ---------------------------------------------------------------------------
// PhaseFieldPredictor, round 9: warp-cooperative register-tiled GEMMs.
// (round-7 design + fix: x staging now includes the timestep offset t*10)
// CTA = 256 threads <-> 128 nodes. Thread tile = 8 gates x 8 nodes packed as
// 32 f32x2 accumulators (lanes = node pairs). x/h in shared [k][node] rows,
// weights pre-DUPLICATED {w,w} in shared (zero pack movs in inner loop).
// Per k: 6 LDS.128 + 32 FFMA2 -> FFMA2-pipe bound.
// ---------------------------------------------------------------------------

#define NPLANE 65536            // 256*256
#define WIDTH  64
typedef unsigned long long ull;

__device__ float g_feats[2 * WIDTH * NPLANE];   // 33.5 MB
__device__ float g_tf   [2 * WIDTH * NPLANE];   // 33.5 MB

__device__ __forceinline__ void ffma2(ull& acc, ull a, ull b) {
    asm("fma.rn.f32x2 %0, %1, %2, %0;" : "+l"(acc) : "l"(a), "l"(b));
}
__device__ __forceinline__ ull pk(float lo, float hi) {
    ull r; asm("mov.b64 %0, {%1, %2};" : "=l"(r) : "f"(lo), "f"(hi)); return r;
}
__device__ __forceinline__ void unpk2(float& lo, float& hi, ull v) {
    asm("mov.b64 {%0, %1}, %2;" : "=f"(lo), "=f"(hi) : "l"(v));
}
// one LDS.128 -> two b64 values (saddr 16B aligned)
__device__ __forceinline__ void lds_w2(ull& w0, ull& w1, uint32_t saddr) {
    asm("ld.shared.v2.b64 {%0, %1}, [%2];" : "=l"(w0), "=l"(w1) : "r"(saddr));
}
__device__ __forceinline__ void sts_f4(uint32_t saddr, float a, float b,
                                       float c, float d) {
    asm volatile("st.shared.v4.f32 [%0], {%1,%2,%3,%4};"
                 :: "r"(saddr), "f"(a), "f"(b), "f"(c), "f"(d));
}

__device__ __forceinline__ float fsig(float x) {
    return __fdividef(1.f, 1.f + __expf(-x));
}
__device__ __forceinline__ float ftanh(float x) {
    x = fminf(fmaxf(x, -15.f), 15.f);
    float e = __expf(2.f * x);
    return __fdividef(e - 1.f, e + 1.f);
}

// Register-tiled GEMM accumulate: GD "output" slots x 4 node-pairs.
// waddr: thread's slice of duplicated-weight row k=0 (GD ull, 16B aligned).
// xaddr: thread's 8 nodes in value row k=0 (32B).
// WROWB: weight row stride bytes; x row stride fixed 512B (128 floats).
template<int K, int GD, int WROWB>
__device__ __forceinline__ void gemmT(ull* __restrict__ acc,
                                      uint32_t waddr, uint32_t xaddr)
{
    #pragma unroll 4
    for (int k = 0; k < K; k++) {
        ull w[GD];
        #pragma unroll
        for (int q = 0; q < GD / 2; q++)
            lds_w2(w[2 * q], w[2 * q + 1], waddr + q * 16);
        ull xx[4];
        lds_w2(xx[0], xx[1], xaddr);
        lds_w2(xx[2], xx[3], xaddr + 16);
        #pragma unroll
        for (int gd = 0; gd < GD; gd++)
            #pragma unroll
            for (int np = 0; np < 4; np++)
                ffma2(acc[gd * 4 + np], xx[np], w[gd]);
        waddr += WROWB;
        xaddr += 512;
    }
}

// ---------------------------------------------------------------------------
// LSTM shared layout (float units; ull arrays occupy 2 floats/elem).
// Weight columns permuted: pcol = jp*8 + g*2 + d  <->  row r = g*32 + 2*jp + d
// ---------------------------------------------------------------------------
#define OWI0  0        // dup Wih0^T [10][128] ull  -> 2560 floats
#define OWH0  2560     // dup Whh0^T [32][128] ull  -> 8192
#define OWI1  10752    // dup Wih1^T
#define OWH1  18944    // dup Whh1^T
#define OB0   27136    // dup bias0 [128] ull -> 256
#define OB1   27392    // dup bias1
#define OF1   27648    // dup fc1^T [32][64] ull -> 4096
#define OF1B  31744    // dup fc1b [64] ull -> 128
#define OXB   31872    // x buffer [10][128] -> 1280
#define OH0   33152    // h0 buffer [32][128] -> 4096
#define OH1   37248    // h1 buffer [32][128] -> 4096
#define LSTM_SMEM_FLOATS 41344
#define LSTM_SMEM_BYTES  (LSTM_SMEM_FLOATS * 4)    // 165376

// LSTM gate epilogue for one layer: acc[(g*2+d)*4+np], c-state cst[2][8],
// writes h-new into Hbuf rows 2*jp+d at this thread's 8 nodes.
__device__ __forceinline__ void gate_epilogue(
    const ull* __restrict__ acc, float* __restrict__ cst /*[16]*/,
    uint32_t hrow0 /* byte addr Hbuf + nb*4 */, int jp)
{
    #pragma unroll
    for (int d = 0; d < 2; d++) {
        float hn[8];
        #pragma unroll
        for (int np = 0; np < 4; np++) {
            float zi0, zi1, zf0, zf1, zg0, zg1, zo0, zo1;
            unpk2(zi0, zi1, acc[(0 + d) * 4 + np]);
            unpk2(zf0, zf1, acc[(2 + d) * 4 + np]);
            unpk2(zg0, zg1, acc[(4 + d) * 4 + np]);
            unpk2(zo0, zo1, acc[(6 + d) * 4 + np]);
            int n0 = 2 * np;
            float cv = cst[d * 8 + n0];
            cv = fsig(zf0) * cv + fsig(zi0) * ftanh(zg0);
            cst[d * 8 + n0] = cv;
            hn[n0] = fsig(zo0) * ftanh(cv);
            cv = cst[d * 8 + n0 + 1];
            cv = fsig(zf1) * cv + fsig(zi1) * ftanh(zg1);
            cst[d * 8 + n0 + 1] = cv;
            hn[n0 + 1] = fsig(zo1) * ftanh(cv);
        }
        uint32_t a = hrow0 + (2 * jp + d) * 512;
        sts_f4(a,      hn[0], hn[1], hn[2], hn[3]);
        sts_f4(a + 16, hn[4], hn[5], hn[6], hn[7]);
    }
}

__global__ __launch_bounds__(256) void lstm_kernel(
    const float* __restrict__ x,
    const float* __restrict__ Wih0, const float* __restrict__ Whh0,
    const float* __restrict__ bih0, const float* __restrict__ bhh0,
    const float* __restrict__ Wih1, const float* __restrict__ Whh1,
    const float* __restrict__ bih1, const float* __restrict__ bhh1,
    const float* __restrict__ fc1w, const float* __restrict__ fc1b)
{
    extern __shared__ float sm[];
    int tid = threadIdx.x;

    // --- stage permuted + duplicated weights ---
    ull* WI0 = reinterpret_cast<ull*>(&sm[OWI0]);
    ull* WH0 = reinterpret_cast<ull*>(&sm[OWH0]);
    ull* WI1 = reinterpret_cast<ull*>(&sm[OWI1]);
    ull* WH1 = reinterpret_cast<ull*>(&sm[OWH1]);
    ull* B0  = reinterpret_cast<ull*>(&sm[OB0]);
    ull* B1  = reinterpret_cast<ull*>(&sm[OB1]);
    ull* F1  = reinterpret_cast<ull*>(&sm[OF1]);
    ull* F1B = reinterpret_cast<ull*>(&sm[OF1B]);

    for (int idx = tid; idx < 10 * 128; idx += 256) {
        int k = idx >> 7, pcol = idx & 127;
        int jp = pcol >> 3, rem = pcol & 7, g = rem >> 1, d = rem & 1;
        int r = g * 32 + 2 * jp + d;
        float v = Wih0[r * 10 + k];
        WI0[idx] = pk(v, v);
    }
    for (int idx = tid; idx < 32 * 128; idx += 256) {
        int k = idx >> 7, pcol = idx & 127;
        int jp = pcol >> 3, rem = pcol & 7, g = rem >> 1, d = rem & 1;
        int r = g * 32 + 2 * jp + d;
        float v0 = Whh0[r * 32 + k];
        float v1 = Wih1[r * 32 + k];
        float v2 = Whh1[r * 32 + k];
        WH0[idx] = pk(v0, v0);
        WI1[idx] = pk(v1, v1);
        WH1[idx] = pk(v2, v2);
    }
    if (tid < 128) {
        int pcol = tid;
        int jp = pcol >> 3, rem = pcol & 7, g = rem >> 1, d = rem & 1;
        int r = g * 32 + 2 * jp + d;
        float v0 = bih0[r] + bhh0[r];
        float v1 = bih1[r] + bhh1[r];
        B0[pcol] = pk(v0, v0);
        B1[pcol] = pk(v1, v1);
    }
    for (int idx = tid; idx < 32 * 64; idx += 256) {
        int k = idx >> 6, o = idx & 63;
        float v = fc1w[o * 32 + k];
        F1[idx] = pk(v, v);
    }
    if (tid < 64) { float v = fc1b[tid]; F1B[tid] = pk(v, v); }
    // zero H0/H1
    for (int idx = tid; idx < 8192; idx += 256) sm[OH0 + idx] = 0.f;
    __syncthreads();

    // --- thread tile mapping ---
    int jp = tid >> 4;            // 0..15 -> gate j-pair
    int ng = tid & 15;            // 0..15 -> node group
    int nb = ng * 8;              // node base within CTA

    int node0 = (blockIdx.x << 7) & (NPLANE - 1);
    int b = blockIdx.x >> 9;
    const float* xg = x + (size_t)b * 50 * NPLANE + node0;

    uint32_t sbase = (uint32_t)__cvta_generic_to_shared(sm);
    uint32_t aWI0 = sbase + OWI0 * 4 + jp * 64;
    uint32_t aWH0 = sbase + OWH0 * 4 + jp * 64;
    uint32_t aWI1 = sbase + OWI1 * 4 + jp * 64;
    uint32_t aWH1 = sbase + OWH1 * 4 + jp * 64;
    uint32_t aXB  = sbase + OXB * 4 + nb * 4;
    uint32_t aH0  = sbase + OH0 * 4 + nb * 4;
    uint32_t aH1  = sbase + OH1 * 4 + nb * 4;

    float c0[16], c1[16];
    #pragma unroll
    for (int k = 0; k < 16; k++) { c0[k] = 0.f; c1[k] = 0.f; }

    #pragma unroll 1
    for (int t = 0; t < 5; t++) {
        // stage x[t] into XB [10][128]  (FIX: include timestep offset t*10)
        for (int idx = tid; idx < 1280; idx += 256)
            sm[OXB + idx] =
                xg[(size_t)(t * 10 + (idx >> 7)) * NPLANE + (idx & 127)];
        __syncthreads();

        // layer 0: gates = Wih0@x + Whh0@h0 + b0
        ull acc[32];
        #pragma unroll
        for (int gd = 0; gd < 8; gd++) {
            ull bv = B0[jp * 8 + gd];
            #pragma unroll
            for (int np = 0; np < 4; np++) acc[gd * 4 + np] = bv;
        }
        gemmT<10, 8, 1024>(acc, aWI0, aXB);
        gemmT<32, 8, 1024>(acc, aWH0, aH0);
        __syncthreads();                       // all reads of old H0 done
        gate_epilogue(acc, c0, aH0, jp);       // write new h0
        __syncthreads();

        // layer 1: gates = Wih1@h0 + Whh1@h1 + b1
        #pragma unroll
        for (int gd = 0; gd < 8; gd++) {
            ull bv = B1[jp * 8 + gd];
            #pragma unroll
            for (int np = 0; np < 4; np++) acc[gd * 4 + np] = bv;
        }
        gemmT<32, 8, 1024>(acc, aWI1, aH0);
        gemmT<32, 8, 1024>(acc, aWH1, aH1);
        __syncthreads();                       // all reads of old H1 done
        gate_epilogue(acc, c1, aH1, jp);       // write new h1
        __syncthreads();
    }

    // fc1 + relu -> g_feats. Thread tile: 4 outs (jp*4..) x 8 nodes.
    {
        ull facc[16];
        #pragma unroll
        for (int o = 0; o < 4; o++) {
            ull bv = F1B[jp * 4 + o];
            #pragma unroll
            for (int np = 0; np < 4; np++) facc[o * 4 + np] = bv;
        }
        gemmT<32, 4, 512>(facc, sbase + OF1 * 4 + jp * 32, aH1);
        float* fo = g_feats + ((size_t)b * WIDTH << 16) + node0 + nb;
        #pragma unroll
        for (int o = 0; o < 4; o++) {
            float r0, r1, r2, r3, r4, r5, r6, r7;
            unpk2(r0, r1, facc[o * 4 + 0]);
            unpk2(r2, r3, facc[o * 4 + 1]);
            unpk2(r4, r5, facc[o * 4 + 2]);
            unpk2(r6, r7, facc[o * 4 + 3]);
            float4 v0 = make_float4(fmaxf(r0, 0.f), fmaxf(r1, 0.f),
                                    fmaxf(r2, 0.f), fmaxf(r3, 0.f));
            float4 v1 = make_float4(fmaxf(r4, 0.f), fmaxf(r5, 0.f),
                                    fmaxf(r6, 0.f), fmaxf(r7, 0.f));
            float* po = fo + ((size_t)(jp * 4 + o) << 16);
            *reinterpret_cast<float4*>(po) = v0;
            *reinterpret_cast<float4*>(po + 4) = v1;
        }
    }
}

// ---------------------------------------------------------------------------
// Graph conv step A: tf = feats @ W, warp-cooperative tiles.
// smem: dup W [64 k][64 out] ull (32KB) + feats tile [64][128] (32KB).
// ---------------------------------------------------------------------------
#define GCV_SMEM_BYTES (16384 * 4)    // 8192 dupW floats + 8192 XF floats

__global__ __launch_bounds__(256) void gconv_gemm_kernel(const float* __restrict__ W)
{
    extern __shared__ float sm[];
    ull* WD = reinterpret_cast<ull*>(&sm[0]);      // [64][64] ull
    float* XF = &sm[8192];                          // [64][128]
    int tid = threadIdx.x;

    int node0 = (blockIdx.x << 7) & (NPLANE - 1);
    int b = blockIdx.x >> 9;
    const float* f = g_feats + ((size_t)b * WIDTH << 16) + node0;

    for (int idx = tid; idx < 4096; idx += 256) {
        float v = W[idx];
        WD[idx] = pk(v, v);
    }
    for (int idx = tid; idx < 8192; idx += 256)
        XF[idx] = f[(size_t)(idx >> 7) * NPLANE + (idx & 127)];
    __syncthreads();

    int og = tid >> 4;            // 4 outputs: og*4..+3
    int ng = tid & 15;
    int nb = ng * 8;

    uint32_t sbase = (uint32_t)__cvta_generic_to_shared(sm);
    ull acc[16];
    #pragma unroll
    for (int i = 0; i < 16; i++) acc[i] = 0ull;
    gemmT<64, 4, 512>(acc, sbase + og * 32, sbase + 8192 * 4 + nb * 4);

    float* o = g_tf + ((size_t)b * WIDTH << 16) + node0 + nb;
    #pragma unroll
    for (int j = 0; j < 4; j++) {
        float r0, r1, r2, r3, r4, r5, r6, r7;
        unpk2(r0, r1, acc[j * 4 + 0]);
        unpk2(r2, r3, acc[j * 4 + 1]);
        unpk2(r4, r5, acc[j * 4 + 2]);
        unpk2(r6, r7, acc[j * 4 + 3]);
        float* po = o + ((size_t)(og * 4 + j) << 16);
        *reinterpret_cast<float4*>(po)     = make_float4(r0, r1, r2, r3);
        *reinterpret_cast<float4*>(po + 4) = make_float4(r4, r5, r6, r7);
    }
}

// ---------------------------------------------------------------------------
// Graph conv step B: 8-neighbor gaussian stencil, float4 vectorized.
// ---------------------------------------------------------------------------
__global__ __launch_bounds__(256) void gconv_stencil_kernel(
    const float* __restrict__ convb, const float* __restrict__ gparam,
    int layer, int dorelu)
{
    int idx4 = blockIdx.x * 256 + threadIdx.x;   // float4 id
    int n4 = idx4 & 16383;
    int p = idx4 >> 14;                          // b*64 + c
    int c = p & 63;
    int i = n4 >> 6;
    int q = n4 & 63;
    int n = n4 << 2;

    float g = gparam[layer];
    float inv = __fdividef(1.f, g * g + 1e-8f);
    float gax = __expf(-inv);
    float gdi = __expf(-2.f * inv);

    const float* tf = g_tf + ((size_t)p << 16);
    const float4* tf4 = reinterpret_cast<const float4*>(tf);

    bool up = (i > 0), dn = (i < 255), lf = (q > 0), rt = (q < 63);

    float4 cm = tf4[n4];
    float4 um = up ? tf4[n4 - 64] : make_float4(0, 0, 0, 0);
    float4 dm = dn ? tf4[n4 + 64] : make_float4(0, 0, 0, 0);
    float clf = lf ? tf[n - 1]   : 0.f;
    float crt = rt ? tf[n + 4]   : 0.f;
    float ulf = (up && lf) ? tf[n - 257] : 0.f;
    float urt = (up && rt) ? tf[n - 252] : 0.f;
    float dlf = (dn && lf) ? tf[n + 255] : 0.f;
    float drt = (dn && rt) ? tf[n + 260] : 0.f;

    float bias = convb[c];

    float4 r;
    r.x = cm.x + gax * (clf  + cm.y + um.x + dm.x) + gdi * (ulf  + um.y + dlf  + dm.y) + bias;
    r.y = cm.y + gax * (cm.x + cm.z + um.y + dm.y) + gdi * (um.x + um.z + dm.x + dm.z) + bias;
    r.z = cm.z + gax * (cm.y + cm.w + um.z + dm.z) + gdi * (um.y + um.w + dm.y + dm.w) + bias;
    r.w = cm.w + gax * (cm.z + crt  + um.w + dm.w) + gdi * (um.z + urt  + dm.z + drt ) + bias;

    if (dorelu) {
        r.x = fmaxf(r.x, 0.f); r.y = fmaxf(r.y, 0.f);
        r.z = fmaxf(r.z, 0.f); r.w = fmaxf(r.w, 0.f);
    }
    reinterpret_cast<float4*>(g_feats)[idx4] = r;
}

// ---------------------------------------------------------------------------
// Head: y = relu(fc2@f + b2); out = fc3@y + b3. Warp-coop fc2, per-node fc3.
// smem floats: s2w dup [64][32] ull @0 (4096), XF @4096 (8192), Y @12288
// (4096), s3w @16384 (320), s2b dup @16704 (64), s3b @16768 (16) -> 16784.
// ---------------------------------------------------------------------------
#define HEAD_SMEM_FLOATS 16784
#define HEAD_SMEM_BYTES  (HEAD_SMEM_FLOATS * 4)

__global__ __launch_bounds__(256) void head_kernel(
    const float* __restrict__ fc2w, const float* __restrict__ fc2b,
    const float* __restrict__ fc3w, const float* __restrict__ fc3b,
    float* __restrict__ out)
{
    extern __shared__ float sm[];
    ull* W2 = reinterpret_cast<ull*>(&sm[0]);       // [64 k][32 p]
    float* XF = &sm[4096];
    float* Y  = &sm[12288];
    float* W3 = &sm[16384];
    ull* B2 = reinterpret_cast<ull*>(&sm[16704]);
    float* B3 = &sm[16768];
    int tid = threadIdx.x;

    int node0 = (blockIdx.x << 7) & (NPLANE - 1);
    int b = blockIdx.x >> 9;
    const float* f = g_feats + ((size_t)b * WIDTH << 16) + node0;

    for (int idx = tid; idx < 2048; idx += 256) {
        int k = idx >> 5, p = idx & 31;
        float v = fc2w[p * 64 + k];
        W2[idx] = pk(v, v);
    }
    for (int idx = tid; idx < 8192; idx += 256)
        XF[idx] = f[(size_t)(idx >> 7) * NPLANE + (idx & 127)];
    for (int idx = tid; idx < 320; idx += 256) W3[idx] = fc3w[idx];
    if (tid < 32) { float v = fc2b[tid]; B2[tid] = pk(v, v); }
    if (tid < 10) B3[tid] = fc3b[tid];
    __syncthreads();

    int og = tid >> 4;            // 2 outputs: og*2, og*2+1
    int ng = tid & 15;
    int nb = ng * 8;

    uint32_t sbase = (uint32_t)__cvta_generic_to_shared(sm);
    ull acc[8];
    #pragma unroll
    for (int o = 0; o < 2; o++) {
        ull bv = B2[og * 2 + o];
        #pragma unroll
        for (int np = 0; np < 4; np++) acc[o * 4 + np] = bv;
    }
    gemmT<64, 2, 256>(acc, sbase + og * 16, sbase + 4096 * 4 + nb * 4);

    uint32_t aY = sbase + 12288 * 4 + nb * 4;
    #pragma unroll
    for (int o = 0; o < 2; o++) {
        float r0, r1, r2, r3, r4, r5, r6, r7;
        unpk2(r0, r1, acc[o * 4 + 0]);
        unpk2(r2, r3, acc[o * 4 + 1]);
        unpk2(r4, r5, acc[o * 4 + 2]);
        unpk2(r6, r7, acc[o * 4 + 3]);
        uint32_t a = aY + (og * 2 + o) * 512;
        sts_f4(a,      fmaxf(r0, 0.f), fmaxf(r1, 0.f), fmaxf(r2, 0.f), fmaxf(r3, 0.f));
        sts_f4(a + 16, fmaxf(r4, 0.f), fmaxf(r5, 0.f), fmaxf(r6, 0.f), fmaxf(r7, 0.f));
    }
    __syncthreads();

    // fc3: 256 threads = 2 oc-halves x 128 nodes
    int node = tid & 127;
    int half = tid >> 7;
    float y[32];
    #pragma unroll
    for (int p = 0; p < 32; p++) y[p] = Y[p * 128 + node];
    #pragma unroll
    for (int j = 0; j < 5; j++) {
        int oc = half * 5 + j;
        float s = B3[oc];
        #pragma unroll
        for (int p = 0; p < 32; p++) s = fmaf(W3[oc * 32 + p], y[p], s);
        out[((size_t)(b * 10 + oc) << 16) + node0 + node] = s;
    }
}

// ---------------------------------------------------------------------------
// Host launch
// ---------------------------------------------------------------------------
extern "C" void kernel_launch(void* const* d_in, const int* in_sizes, int n_in,
                              void* d_out, int out_size)
{
    const float* x     = (const float*)d_in[0];
    // d_in[1..3]: edge lists — fixed 8-neighbor grid, implemented as stencil.
    const float* Wih0  = (const float*)d_in[4];
    const float* Whh0  = (const float*)d_in[5];
    const float* bih0  = (const float*)d_in[6];
    const float* bhh0  = (const float*)d_in[7];
    const float* Wih1  = (const float*)d_in[8];
    const float* Whh1  = (const float*)d_in[9];
    const float* bih1  = (const float*)d_in[10];
    const float* bhh1  = (const float*)d_in[11];
    const float* fc1w  = (const float*)d_in[12];
    const float* fc1b  = (const float*)d_in[13];
    const float* convw = (const float*)d_in[14];
    const float* convb = (const float*)d_in[15];
    const float* gparam= (const float*)d_in[16];
    const float* fc2w  = (const float*)d_in[17];
    const float* fc2b  = (const float*)d_in[18];
    const float* fc3w  = (const float*)d_in[19];
    const float* fc3b  = (const float*)d_in[20];
    float* out = (float*)d_out;

    cudaFuncSetAttribute(lstm_kernel,
                         cudaFuncAttributeMaxDynamicSharedMemorySize,
                         LSTM_SMEM_BYTES);
    cudaFuncSetAttribute(gconv_gemm_kernel,
                         cudaFuncAttributeMaxDynamicSharedMemorySize,
                         GCV_SMEM_BYTES);
    cudaFuncSetAttribute(head_kernel,
                         cudaFuncAttributeMaxDynamicSharedMemorySize,
                         HEAD_SMEM_BYTES);

    // 131072 nodes / 128 per CTA = 1024 CTAs
    lstm_kernel<<<1024, 256, LSTM_SMEM_BYTES>>>(
        x, Wih0, Whh0, bih0, bhh0, Wih1, Whh1, bih1, bhh1, fc1w, fc1b);

    for (int k = 0; k < 4; k++) {
        gconv_gemm_kernel<<<1024, 256, GCV_SMEM_BYTES>>>(convw + (size_t)k * 4096);
        gconv_stencil_kernel<<<8192, 256>>>(
            convb + (size_t)k * 64, gparam, k, (k != 3) ? 1 : 0);
    }

    head_kernel<<<1024, 256, HEAD_SMEM_BYTES>>>(fc2w, fc2b, fc3w, fc3b, out);
}

// round 11
// speedup vs baseline: 1.3488x; 1.3488x over previous
#include <cuda_runtime.h>
#include <cuda_bf16.h>
#include <cstdint>

// ---------------------------------------------------------------------------
// PhaseFieldPredictor, round 10: round-5 architecture (best known, 782us):
// 2 nodes/thread, private packed x/h in regs, broadcast weight LDS.128 via
// ld.shared.v2.b64 feeding 4 FFMA2. Changes vs round 5: j-loop unroll 2 in
// the LSTM cell (overlap epilogue MUFU chains with next j's dots) and
// unroll 4 in the gconv GEMM j-loop.
// ---------------------------------------------------------------------------

#define NPLANE 65536            // 256*256
#define BN     131072           // 2 * 65536
#define WIDTH  64
typedef unsigned long long ull;

__device__ float g_feats[2 * WIDTH * NPLANE];   // 33.5 MB
__device__ float g_tf   [2 * WIDTH * NPLANE];   // 33.5 MB

__device__ __forceinline__ void ffma2(ull& acc, ull a, ull b) {
    asm("fma.rn.f32x2 %0, %1, %2, %0;" : "+l"(acc) : "l"(a), "l"(b));
}
__device__ __forceinline__ ull pk(float lo, float hi) {
    ull r; asm("mov.b64 %0, {%1, %2};" : "=l"(r) : "f"(lo), "f"(hi)); return r;
}
__device__ __forceinline__ float red2(ull v) {
    float lo, hi; asm("mov.b64 {%0, %1}, %2;" : "=f"(lo), "=f"(hi) : "l"(v));
    return lo + hi;
}
// one LDS.128 -> two packed-f32x2 weight pairs (saddr 16B aligned)
__device__ __forceinline__ void lds_w2(ull& w0, ull& w1, uint32_t saddr) {
    asm("ld.shared.v2.b64 {%0, %1}, [%2];" : "=l"(w0), "=l"(w1) : "r"(saddr));
}

__device__ __forceinline__ float fsig(float x) {
    return __fdividef(1.f, 1.f + __expf(-x));
}
__device__ __forceinline__ float ftanh(float x) {
    x = fminf(fmaxf(x, -15.f), 15.f);
    float e = __expf(2.f * x);
    return __fdividef(e - 1.f, e + 1.f);
}

// 2-node packed dot: one weight load feeds 4 FFMA2.
template<int NPAIR>
__device__ __forceinline__ void dot4(ull& aA0, ull& aA1, ull& aB0, ull& aB1,
                                     uint32_t waddr,
                                     const ull* __restrict__ vA,
                                     const ull* __restrict__ vB)
{
    #pragma unroll
    for (int p = 0; p < NPAIR / 2; p++) {
        ull w0, w1;
        lds_w2(w0, w1, waddr + p * 16);
        ffma2(aA0, vA[2 * p],     w0);
        ffma2(aB0, vB[2 * p],     w0);
        ffma2(aA1, vA[2 * p + 1], w1);
        ffma2(aB1, vB[2 * p + 1], w1);
    }
}

// ---------------------------------------------------------------------------
// Shared layout (float units) -- weights only, 66KB.
// ---------------------------------------------------------------------------
#define OFF_WIH0  0        // 128 rows * 12 (10 data + 2 zero pad)
#define OFF_WHH0  1536     // 128*32
#define OFF_WIH1  5632     // 128*32
#define OFF_WHH1  9728     // 128*32
#define OFF_B0    13824    // 128 ull packed {bias,0} = 256 floats
#define OFF_B1    14080    // 256
#define OFF_FC1W  14336    // 64*32
#define OFF_FC1B  16384    // 64 ull = 128 floats
#define LSTM_SMEM_FLOATS 16512
#define LSTM_SMEM_BYTES  (LSTM_SMEM_FLOATS * 4)   // 66 KB

// One LSTM cell for a node pair. XPAIR = input pairs, WSTB = Wih row bytes.
// Gate order (torch): rows [0:32)=i, [32:64)=f, [64:96)=g, [96:128)=o.
template<int XPAIR, int WSTB>
__device__ __forceinline__ void cell2(
    const ull* __restrict__ xA, const ull* __restrict__ xB,
    ull* __restrict__ hA, ull* __restrict__ hB,
    float* __restrict__ cA, float* __restrict__ cB,        // local [32]
    float* __restrict__ hnA, float* __restrict__ hnB,      // local [32]
    uint32_t aWih, uint32_t aWhh, const ull* __restrict__ Bp)
{
    #pragma unroll 2
    for (int j = 0; j < 32; j++) {
        float zA[4], zB[4];
        #pragma unroll
        for (int g = 0; g < 4; g++) {
            ull b = Bp[g * 32 + j];
            ull aA0 = b, aA1 = 0ull, aB0 = b, aB1 = 0ull;
            dot4<XPAIR>(aA0, aA1, aB0, aB1, aWih + (g * 32 + j) * WSTB, xA, xB);
            dot4<16>(aA0, aA1, aB0, aB1, aWhh + (g * 32 + j) * 128, hA, hB);
            zA[g] = red2(aA0) + red2(aA1);
            zB[g] = red2(aB0) + red2(aB1);
        }
        float cv = cA[j];
        cv = fsig(zA[1]) * cv + fsig(zA[0]) * ftanh(zA[2]);
        cA[j] = cv;
        hnA[j] = fsig(zA[3]) * ftanh(cv);

        cv = cB[j];
        cv = fsig(zB[1]) * cv + fsig(zB[0]) * ftanh(zB[2]);
        cB[j] = cv;
        hnB[j] = fsig(zB[3]) * ftanh(cv);
    }
    #pragma unroll
    for (int k = 0; k < 16; k++) {
        hA[k] = pk(hnA[2 * k], hnA[2 * k + 1]);
        hB[k] = pk(hnB[2 * k], hnB[2 * k + 1]);
    }
}

__global__ __launch_bounds__(256) void lstm_kernel(
    const float* __restrict__ x,
    const float* __restrict__ Wih0, const float* __restrict__ Whh0,
    const float* __restrict__ bih0, const float* __restrict__ bhh0,
    const float* __restrict__ Wih1, const float* __restrict__ Whh1,
    const float* __restrict__ bih1, const float* __restrict__ bhh1,
    const float* __restrict__ fc1w, const float* __restrict__ fc1b)
{
    extern __shared__ float sm[];
    int tid = threadIdx.x;

    for (int i = tid; i < 128 * 12; i += 256) {
        int r = i / 12, col = i % 12;
        sm[OFF_WIH0 + i] = (col < 10) ? Wih0[r * 10 + col] : 0.f;
    }
    for (int i = tid; i < 128 * 32; i += 256) {
        sm[OFF_WHH0 + i] = Whh0[i];
        sm[OFF_WIH1 + i] = Wih1[i];
        sm[OFF_WHH1 + i] = Whh1[i];
    }
    if (tid < 128) {
        reinterpret_cast<ull*>(&sm[OFF_B0])[tid] = pk(bih0[tid] + bhh0[tid], 0.f);
        reinterpret_cast<ull*>(&sm[OFF_B1])[tid] = pk(bih1[tid] + bhh1[tid], 0.f);
    }
    for (int i = tid; i < 64 * 32; i += 256) sm[OFF_FC1W + i] = fc1w[i];
    if (tid < 64)
        reinterpret_cast<ull*>(&sm[OFF_FC1B])[tid] = pk(fc1b[tid], 0.f);
    __syncthreads();

    int pairid = blockIdx.x * 256 + tid;         // 0..65535
    int b = pairid >> 15;
    int n0 = (pairid & 32767) * 2;
    const float* xb = x + (size_t)b * 50 * NPLANE + n0;

    uint32_t sbase = (uint32_t)__cvta_generic_to_shared(sm);
    uint32_t aW0i = sbase + OFF_WIH0 * 4;
    uint32_t aW0h = sbase + OFF_WHH0 * 4;
    uint32_t aW1i = sbase + OFF_WIH1 * 4;
    uint32_t aW1h = sbase + OFF_WHH1 * 4;
    const ull* B0 = reinterpret_cast<const ull*>(&sm[OFF_B0]);
    const ull* B1 = reinterpret_cast<const ull*>(&sm[OFF_B1]);

    // per-thread state: h packed in registers, c / h-new staging in local
    ull h0A[16], h0B[16], h1A[16], h1B[16];
    #pragma unroll
    for (int k = 0; k < 16; k++) {
        h0A[k] = 0ull; h0B[k] = 0ull; h1A[k] = 0ull; h1B[k] = 0ull;
    }
    float cA0[32], cB0[32], cA1[32], cB1[32], hnA[32], hnB[32];
    #pragma unroll
    for (int k = 0; k < 32; k++) {
        cA0[k] = 0.f; cB0[k] = 0.f; cA1[k] = 0.f; cB1[k] = 0.f;
    }

    for (int t = 0; t < 5; t++) {
        float2 v[10];
        #pragma unroll
        for (int c = 0; c < 10; c++)
            v[c] = *reinterpret_cast<const float2*>(xb + ((size_t)(t * 10 + c) << 16));
        ull xA[6], xB[6];
        #pragma unroll
        for (int k = 0; k < 5; k++) {
            xA[k] = pk(v[2 * k].x, v[2 * k + 1].x);
            xB[k] = pk(v[2 * k].y, v[2 * k + 1].y);
        }
        xA[5] = 0ull; xB[5] = 0ull;    // matches zero-padded weight cols 10,11

        cell2<6, 48>(xA, xB, h0A, h0B, cA0, cB0, hnA, hnB, aW0i, aW0h, B0);
        cell2<16, 128>(h0A, h0B, h1A, h1B, cA1, cB1, hnA, hnB, aW1i, aW1h, B1);
    }

    // fused fc1 + relu -> feats (channel-major), float2 per pair
    uint32_t aF1 = sbase + OFF_FC1W * 4;
    const ull* FB = reinterpret_cast<const ull*>(&sm[OFF_FC1B]);
    float* fo = g_feats + ((size_t)b * WIDTH << 16) + n0;
    #pragma unroll 1
    for (int j = 0; j < WIDTH; j++) {
        ull bj = FB[j];
        ull aA0 = bj, aA1 = 0ull, aB0 = bj, aB1 = 0ull;
        dot4<16>(aA0, aA1, aB0, aB1, aF1 + j * 128, h1A, h1B);
        float2 r;
        r.x = fmaxf(red2(aA0) + red2(aA1), 0.f);
        r.y = fmaxf(red2(aB0) + red2(aB1), 0.f);
        *reinterpret_cast<float2*>(fo + ((size_t)j << 16)) = r;
    }
}

// ---------------------------------------------------------------------------
// Graph conv step A: tf = feats @ W, 2 nodes/thread, transposed weights.
// ---------------------------------------------------------------------------
__global__ __launch_bounds__(256) void gconv_gemm_kernel(const float* __restrict__ W)
{
    __shared__ __align__(16) float sWT[64 * 64];
    int tid = threadIdx.x;
    for (int idx = tid; idx < 4096; idx += 256) {
        int j = idx >> 6, i = idx & 63;
        sWT[idx] = W[i * 64 + j];
    }
    __syncthreads();

    int pairid = blockIdx.x * 256 + tid;     // 0..65535
    int b = pairid >> 15;
    int n0 = (pairid & 32767) * 2;
    const float* f = g_feats + ((size_t)b * WIDTH << 16) + n0;

    ull xA[32], xB[32];
    #pragma unroll
    for (int k = 0; k < 32; k++) {
        float2 v0 = *reinterpret_cast<const float2*>(f + ((size_t)(2 * k) << 16));
        float2 v1 = *reinterpret_cast<const float2*>(f + ((size_t)(2 * k + 1) << 16));
        xA[k] = pk(v0.x, v1.x);
        xB[k] = pk(v0.y, v1.y);
    }

    uint32_t aW = (uint32_t)__cvta_generic_to_shared(sWT);
    float* o = g_tf + ((size_t)b * WIDTH << 16) + n0;
    #pragma unroll 4
    for (int j = 0; j < WIDTH; j++) {
        ull aA0 = 0ull, aA1 = 0ull, aB0 = 0ull, aB1 = 0ull;
        dot4<32>(aA0, aA1, aB0, aB1, aW + j * 256, xA, xB);
        float2 r;
        r.x = red2(aA0) + red2(aA1);
        r.y = red2(aB0) + red2(aB1);
        *reinterpret_cast<float2*>(o + ((size_t)j << 16)) = r;
    }
}

// ---------------------------------------------------------------------------
// Graph conv step B: 8-neighbor gaussian stencil, float4 vectorized.
// ---------------------------------------------------------------------------
__global__ __launch_bounds__(256) void gconv_stencil_kernel(
    const float* __restrict__ convb, const float* __restrict__ gparam,
    int layer, int dorelu)
{
    int idx4 = blockIdx.x * 256 + threadIdx.x;   // float4 id
    int n4 = idx4 & 16383;
    int p = idx4 >> 14;                          // b*64 + c
    int c = p & 63;
    int i = n4 >> 6;
    int q = n4 & 63;
    int n = n4 << 2;

    float g = gparam[layer];
    float inv = __fdividef(1.f, g * g + 1e-8f);
    float gax = __expf(-inv);
    float gdi = __expf(-2.f * inv);

    const float* tf = g_tf + ((size_t)p << 16);
    const float4* tf4 = reinterpret_cast<const float4*>(tf);

    bool up = (i > 0), dn = (i < 255), lf = (q > 0), rt = (q < 63);

    float4 cm = tf4[n4];
    float4 um = up ? tf4[n4 - 64] : make_float4(0, 0, 0, 0);
    float4 dm = dn ? tf4[n4 + 64] : make_float4(0, 0, 0, 0);
    float clf = lf ? tf[n - 1]   : 0.f;
    float crt = rt ? tf[n + 4]   : 0.f;
    float ulf = (up && lf) ? tf[n - 257] : 0.f;
    float urt = (up && rt) ? tf[n - 252] : 0.f;
    float dlf = (dn && lf) ? tf[n + 255] : 0.f;
    float drt = (dn && rt) ? tf[n + 260] : 0.f;

    float bias = convb[c];

    float4 r;
    r.x = cm.x + gax * (clf  + cm.y + um.x + dm.x) + gdi * (ulf  + um.y + dlf  + dm.y) + bias;
    r.y = cm.y + gax * (cm.x + cm.z + um.y + dm.y) + gdi * (um.x + um.z + dm.x + dm.z) + bias;
    r.z = cm.z + gax * (cm.y + cm.w + um.z + dm.z) + gdi * (um.y + um.w + dm.y + dm.w) + bias;
    r.w = cm.w + gax * (cm.z + crt  + um.w + dm.w) + gdi * (um.z + urt  + dm.z + drt ) + bias;

    if (dorelu) {
        r.x = fmaxf(r.x, 0.f); r.y = fmaxf(r.y, 0.f);
        r.z = fmaxf(r.z, 0.f); r.w = fmaxf(r.w, 0.f);
    }
    reinterpret_cast<float4*>(g_feats)[idx4] = r;
}

// ---------------------------------------------------------------------------
// Head: out = relu(feats @ fc2^T + b2) @ fc3^T + b3, 2 nodes/thread.
// ---------------------------------------------------------------------------
__global__ __launch_bounds__(256) void head_kernel(
    const float* __restrict__ fc2w, const float* __restrict__ fc2b,
    const float* __restrict__ fc3w, const float* __restrict__ fc3b,
    float* __restrict__ out)
{
    __shared__ __align__(16) float s2w[32 * 64];
    __shared__ __align__(16) float s3w[10 * 32];
    __shared__ float s2b[32];
    __shared__ float s3b[16];
    int tid = threadIdx.x;
    for (int i = tid; i < 32 * 64; i += 256) s2w[i] = fc2w[i];
    for (int i = tid; i < 10 * 32; i += 256) s3w[i] = fc3w[i];
    if (tid < 32) s2b[tid] = fc2b[tid];
    if (tid < 10) s3b[tid] = fc3b[tid];
    __syncthreads();

    int pairid = blockIdx.x * 256 + tid;     // 0..65535
    int b = pairid >> 15;
    int n0 = (pairid & 32767) * 2;
    const float* f = g_feats + ((size_t)b * WIDTH << 16) + n0;

    ull fA[32], fB[32];
    #pragma unroll
    for (int k = 0; k < 32; k++) {
        float2 v0 = *reinterpret_cast<const float2*>(f + ((size_t)(2 * k) << 16));
        float2 v1 = *reinterpret_cast<const float2*>(f + ((size_t)(2 * k + 1) << 16));
        fA[k] = pk(v0.x, v1.x);
        fB[k] = pk(v0.y, v1.y);
    }

    uint32_t a2 = (uint32_t)__cvta_generic_to_shared(s2w);
    uint32_t a3 = (uint32_t)__cvta_generic_to_shared(s3w);

    float yA[32], yB[32];                    // local staging
    #pragma unroll 1
    for (int p = 0; p < 32; p++) {
        ull aA0 = 0ull, aA1 = 0ull, aB0 = 0ull, aB1 = 0ull;
        dot4<32>(aA0, aA1, aB0, aB1, a2 + p * 256, fA, fB);
        yA[p] = fmaxf(s2b[p] + red2(aA0) + red2(aA1), 0.f);
        yB[p] = fmaxf(s2b[p] + red2(aB0) + red2(aB1), 0.f);
    }
    ull yAp[16], yBp[16];
    #pragma unroll
    for (int k = 0; k < 16; k++) {
        yAp[k] = pk(yA[2 * k], yA[2 * k + 1]);
        yBp[k] = pk(yB[2 * k], yB[2 * k + 1]);
    }

    #pragma unroll
    for (int oc = 0; oc < 10; oc++) {
        ull aA0 = 0ull, aA1 = 0ull, aB0 = 0ull, aB1 = 0ull;
        dot4<16>(aA0, aA1, aB0, aB1, a3 + oc * 128, yAp, yBp);
        float2 r;
        r.x = s3b[oc] + red2(aA0) + red2(aA1);
        r.y = s3b[oc] + red2(aB0) + red2(aB1);
        *reinterpret_cast<float2*>(out + (((size_t)(b * 10 + oc)) << 16) + n0) = r;
    }
}

// ---------------------------------------------------------------------------
// Host launch
// ---------------------------------------------------------------------------
extern "C" void kernel_launch(void* const* d_in, const int* in_sizes, int n_in,
                              void* d_out, int out_size)
{
    const float* x     = (const float*)d_in[0];
    // d_in[1..3]: edge lists — fixed 8-neighbor grid, implemented as stencil.
    const float* Wih0  = (const float*)d_in[4];
    const float* Whh0  = (const float*)d_in[5];
    const float* bih0  = (const float*)d_in[6];
    const float* bhh0  = (const float*)d_in[7];
    const float* Wih1  = (const float*)d_in[8];
    const float* Whh1  = (const float*)d_in[9];
    const float* bih1  = (const float*)d_in[10];
    const float* bhh1  = (const float*)d_in[11];
    const float* fc1w  = (const float*)d_in[12];
    const float* fc1b  = (const float*)d_in[13];
    const float* convw = (const float*)d_in[14];
    const float* convb = (const float*)d_in[15];
    const float* gparam= (const float*)d_in[16];
    const float* fc2w  = (const float*)d_in[17];
    const float* fc2b  = (const float*)d_in[18];
    const float* fc3w  = (const float*)d_in[19];
    const float* fc3b  = (const float*)d_in[20];
    float* out = (float*)d_out;

    cudaFuncSetAttribute(lstm_kernel,
                         cudaFuncAttributeMaxDynamicSharedMemorySize,
                         LSTM_SMEM_BYTES);

    // 65536 node pairs, 256 threads/CTA -> 256 CTAs (round-5 geometry)
    lstm_kernel<<<256, 256, LSTM_SMEM_BYTES>>>(
        x, Wih0, Whh0, bih0, bhh0, Wih1, Whh1, bih1, bhh1, fc1w, fc1b);

    for (int k = 0; k < 4; k++) {
        gconv_gemm_kernel<<<256, 256>>>(convw + (size_t)k * 64 * 64);
        gconv_stencil_kernel<<<(2 * WIDTH * NPLANE / 4) / 256, 256>>>(
            convb + (size_t)k * 64, gparam, k, (k != 3) ? 1 : 0);
    }

    head_kernel<<<256, 256>>>(fc2w, fc2b, fc3w, fc3b, out);
}